// round 4
// baseline (speedup 1.0000x reference)
#include <cuda_runtime.h>
#include <cstdint>

#define FULL_MASK 0xFFFFFFFFu

static constexpr float EPS = 1e-10f;
static constexpr float FAR_DELTA = 1e10f;
static constexpr int P = 128;           // samples per ray
static constexpr int C = 3;             // channels
static constexpr int WARPS_PER_BLOCK = 8;
static constexpr int RAYS_PER_WARP = 2;

// One warp per 2 rays. Each lane owns 4 consecutive samples of each ray.
// 10 independent LDG.128 per lane front-batched; two interleaved warp
// product-scans; register-only feature dot products (fixed permutation).
__global__ __launch_bounds__(256) void volume_render_kernel(
    const float* __restrict__ density,       // [N, P]
    const float* __restrict__ feature,       // [N, P, 3]
    const float* __restrict__ depth_values,  // [N, P]
    float* __restrict__ out,                 // [N*3 feat | N depth]
    int N)
{
    const int warp = threadIdx.x >> 5;
    const int lane = threadIdx.x & 31;
    const int gw   = blockIdx.x * WARPS_PER_BLOCK + warp;
    const int ray0 = gw * RAYS_PER_WARP;
    if (ray0 >= N) return;

    // ---- front-batched independent wide loads: 10 x LDG.128 ----
    float4 d4[2], z4[2], fA[2], fB[2], fC[2];
    #pragma unroll
    for (int j = 0; j < RAYS_PER_WARP; ++j) {
        const size_t base = (size_t)(ray0 + j) * P;
        d4[j] = ((const float4*)(density      + base))[lane];
        z4[j] = ((const float4*)(depth_values + base))[lane];
        const float4* f = ((const float4*)(feature + base * C)) + lane * 3;
        fA[j] = f[0];   // s0.r s0.g s0.b s1.r
        fB[j] = f[1];   // s1.g s1.b s2.r s2.g
        fC[j] = f[2];   // s2.b s3.r s3.g s3.b
    }

    float acc_r[2], acc_g[2], acc_b[2], acc_d[2];
    float ltot[2], pre1[2], pre2[2], pre3[2];
    float a0[2], a1[2], a2[2], a3[2];

    #pragma unroll
    for (int j = 0; j < RAYS_PER_WARP; ++j) {
        // deltas
        const float znext = __shfl_down_sync(FULL_MASK, z4[j].x, 1);
        const float dl0 = z4[j].y - z4[j].x;
        const float dl1 = z4[j].z - z4[j].y;
        const float dl2 = z4[j].w - z4[j].z;
        const float dl3 = (lane == 31) ? FAR_DELTA : (znext - z4[j].w);

        // alpha / cumprod factors
        const float e0 = __expf(-fmaxf(d4[j].x, 0.0f) * dl0);
        const float e1 = __expf(-fmaxf(d4[j].y, 0.0f) * dl1);
        const float e2 = __expf(-fmaxf(d4[j].z, 0.0f) * dl2);
        const float e3 = __expf(-fmaxf(d4[j].w, 0.0f) * dl3);
        a0[j] = 1.0f - e0;
        a1[j] = 1.0f - e1;
        a2[j] = 1.0f - e2;
        a3[j] = 1.0f - e3;
        const float f0 = e0 + EPS, f1 = e1 + EPS, f2 = e2 + EPS, f3 = e3 + EPS;
        pre1[j] = f0;
        pre2[j] = f0 * f1;
        pre3[j] = pre2[j] * f2;
        ltot[j] = pre3[j] * f3;
    }

    // ---- interleaved warp inclusive product scans (2 independent chains) ----
    float v0 = ltot[0], v1 = ltot[1];
    #pragma unroll
    for (int off = 1; off < 32; off <<= 1) {
        const float t0 = __shfl_up_sync(FULL_MASK, v0, off);
        const float t1 = __shfl_up_sync(FULL_MASK, v1, off);
        if (lane >= off) { v0 *= t0; v1 *= t1; }
    }
    float Lex0 = __shfl_up_sync(FULL_MASK, v0, 1);
    float Lex1 = __shfl_up_sync(FULL_MASK, v1, 1);
    if (lane == 0) { Lex0 = 1.0f; Lex1 = 1.0f; }
    const float Lex[2] = {Lex0, Lex1};

    #pragma unroll
    for (int j = 0; j < RAYS_PER_WARP; ++j) {
        const float w0 = Lex[j] * a0[j];
        const float w1 = Lex[j] * pre1[j] * a1[j];
        const float w2 = Lex[j] * pre2[j] * a2[j];
        const float w3 = Lex[j] * pre3[j] * a3[j];

        acc_r[j] = w0 * fA[j].x + w1 * fA[j].w + w2 * fB[j].z + w3 * fC[j].y;
        acc_g[j] = w0 * fA[j].y + w1 * fB[j].x + w2 * fB[j].w + w3 * fC[j].z;
        acc_b[j] = w0 * fA[j].z + w1 * fB[j].y + w2 * fC[j].x + w3 * fC[j].w;
        acc_d[j] = w0 * z4[j].x + w1 * z4[j].y + w2 * z4[j].z + w3 * z4[j].w;
    }

    // ---- warp reduction: 8 independent chains interleaved ----
    #pragma unroll
    for (int off = 16; off > 0; off >>= 1) {
        #pragma unroll
        for (int j = 0; j < RAYS_PER_WARP; ++j) {
            acc_r[j] += __shfl_xor_sync(FULL_MASK, acc_r[j], off);
            acc_g[j] += __shfl_xor_sync(FULL_MASK, acc_g[j], off);
            acc_b[j] += __shfl_xor_sync(FULL_MASK, acc_b[j], off);
            acc_d[j] += __shfl_xor_sync(FULL_MASK, acc_d[j], off);
        }
    }

    // lane j (< 2) writes ray0+j's outputs (all lanes hold the full sums)
    if (lane < RAYS_PER_WARP) {
        const int r = ray0 + lane;
        if (r < N) {
            float* feat_out  = out;                   // [N, 3]
            float* depth_out = out + (size_t)N * C;   // [N]
            feat_out[(size_t)r * C + 0] = acc_r[lane];
            feat_out[(size_t)r * C + 1] = acc_g[lane];
            feat_out[(size_t)r * C + 2] = acc_b[lane];
            depth_out[r] = acc_d[lane];
        }
    }
}

extern "C" void kernel_launch(void* const* d_in, const int* in_sizes, int n_in,
                              void* d_out, int out_size)
{
    const float* density      = (const float*)d_in[0];
    const float* feature      = (const float*)d_in[1];
    const float* depth_values = (const float*)d_in[2];
    float* out = (float*)d_out;

    const int N = in_sizes[0] / P;   // density is [N, P]

    const int rays_per_block = WARPS_PER_BLOCK * RAYS_PER_WARP;  // 16
    const int blocks = (N + rays_per_block - 1) / rays_per_block;
    volume_render_kernel<<<blocks, 256>>>(density, feature, depth_values, out, N);
}

// round 5
// speedup vs baseline: 1.0269x; 1.0269x over previous
#include <cuda_runtime.h>
#include <cstdint>

#define FULL_MASK 0xFFFFFFFFu

static constexpr float EPS = 1e-10f;
static constexpr float FAR_DELTA = 1e10f;
static constexpr int P = 128;           // samples per ray
static constexpr int C = 3;             // channels
static constexpr int WARPS_PER_BLOCK = 4;   // 128-thread blocks

// One warp per ray. Each lane owns 4 consecutive samples.
// 5 independent streaming LDG.128 per lane, one warp product-scan,
// register-only feature dot products (fixed channel permutation).
__global__ __launch_bounds__(128) void volume_render_kernel(
    const float* __restrict__ density,       // [N, P]
    const float* __restrict__ feature,       // [N, P, 3]
    const float* __restrict__ depth_values,  // [N, P]
    float* __restrict__ out,                 // [N*3 feat | N depth]
    int N)
{
    const int warp = threadIdx.x >> 5;
    const int lane = threadIdx.x & 31;
    const int ray  = blockIdx.x * WARPS_PER_BLOCK + warp;
    if (ray >= N) return;

    const float4* dens4 = (const float4*)(density      + (size_t)ray * P);
    const float4* dep4  = (const float4*)(depth_values + (size_t)ray * P);
    // lane's 4 samples' features: 12 consecutive floats at lane*12
    const float4* featL = (const float4*)(feature + (size_t)ray * P * C) + lane * 3;

    // ---- front-batched independent wide streaming loads (5 x LDG.128.CS) ----
    const float4 d4 = __ldcs(&dens4[lane]);
    const float4 z4 = __ldcs(&dep4[lane]);
    const float4 fA = __ldcs(&featL[0]);   // s0.r s0.g s0.b s1.r
    const float4 fB = __ldcs(&featL[1]);   // s1.g s1.b s2.r s2.g
    const float4 fC = __ldcs(&featL[2]);   // s2.b s3.r s3.g s3.b

    // ---- deltas ----
    const float znext = __shfl_down_sync(FULL_MASK, z4.x, 1);  // z[(lane+1)*4]
    const float dl0 = z4.y - z4.x;
    const float dl1 = z4.z - z4.y;
    const float dl2 = z4.w - z4.z;
    const float dl3 = (lane == 31) ? FAR_DELTA : (znext - z4.w);

    // ---- alpha / cumprod factors ----
    const float e0 = __expf(-fmaxf(d4.x, 0.0f) * dl0);
    const float e1 = __expf(-fmaxf(d4.y, 0.0f) * dl1);
    const float e2 = __expf(-fmaxf(d4.z, 0.0f) * dl2);
    const float e3 = __expf(-fmaxf(d4.w, 0.0f) * dl3);
    const float f0 = e0 + EPS, a0 = 1.0f - e0;
    const float f1 = e1 + EPS, a1 = 1.0f - e1;
    const float f2 = e2 + EPS, a2 = 1.0f - e2;
    const float f3 = e3 + EPS, a3 = 1.0f - e3;

    // per-lane exclusive prefix products
    const float pre1 = f0;
    const float pre2 = f0 * f1;
    const float pre3 = pre2 * f2;
    const float ltot = pre3 * f3;

    // ---- warp inclusive product scan over lane totals ----
    float v = ltot;
    #pragma unroll
    for (int off = 1; off < 32; off <<= 1) {
        const float t = __shfl_up_sync(FULL_MASK, v, off);
        if (lane >= off) v *= t;
    }
    float Lex = __shfl_up_sync(FULL_MASK, v, 1);  // product of preceding lanes
    if (lane == 0) Lex = 1.0f;

    // ---- weights ----
    const float w0 = Lex * a0;
    const float w1 = Lex * pre1 * a1;
    const float w2 = Lex * pre2 * a2;
    const float w3 = Lex * pre3 * a3;

    // ---- register-only accumulation (fixed permutation) ----
    float acc_r = w0 * fA.x + w1 * fA.w + w2 * fB.z + w3 * fC.y;
    float acc_g = w0 * fA.y + w1 * fB.x + w2 * fB.w + w3 * fC.z;
    float acc_b = w0 * fA.z + w1 * fB.y + w2 * fC.x + w3 * fC.w;
    float acc_d = w0 * z4.x + w1 * z4.y + w2 * z4.z + w3 * z4.w;

    // ---- warp reduction ----
    #pragma unroll
    for (int off = 16; off > 0; off >>= 1) {
        acc_r += __shfl_xor_sync(FULL_MASK, acc_r, off);
        acc_g += __shfl_xor_sync(FULL_MASK, acc_g, off);
        acc_b += __shfl_xor_sync(FULL_MASK, acc_b, off);
        acc_d += __shfl_xor_sync(FULL_MASK, acc_d, off);
    }

    if (lane == 0) {
        float* feat_out  = out;                   // [N, 3]
        float* depth_out = out + (size_t)N * C;   // [N]
        feat_out[(size_t)ray * C + 0] = acc_r;
        feat_out[(size_t)ray * C + 1] = acc_g;
        feat_out[(size_t)ray * C + 2] = acc_b;
        depth_out[ray] = acc_d;
    }
}

extern "C" void kernel_launch(void* const* d_in, const int* in_sizes, int n_in,
                              void* d_out, int out_size)
{
    const float* density      = (const float*)d_in[0];
    const float* feature      = (const float*)d_in[1];
    const float* depth_values = (const float*)d_in[2];
    float* out = (float*)d_out;

    const int N = in_sizes[0] / P;   // density is [N, P]

    const int blocks = (N + WARPS_PER_BLOCK - 1) / WARPS_PER_BLOCK;
    volume_render_kernel<<<blocks, 128>>>(density, feature, depth_values, out, N);
}

// round 6
// speedup vs baseline: 1.0326x; 1.0055x over previous
#include <cuda_runtime.h>
#include <cstdint>

#define FULL_MASK 0xFFFFFFFFu

static constexpr float EPS = 1e-10f;
static constexpr float FAR_DELTA = 1e10f;
static constexpr int P = 128;           // samples per ray
static constexpr int C = 3;             // channels
static constexpr int WARPS_PER_BLOCK = 2;   // 64-thread blocks: finest scheduling grain

// One warp per ray. Each lane owns 4 consecutive samples.
// 5 independent streaming LDG.128 per lane, one warp product-scan,
// register-only feature dot products (fixed channel permutation).
__global__ __launch_bounds__(64) void volume_render_kernel(
    const float* __restrict__ density,       // [N, P]
    const float* __restrict__ feature,       // [N, P, 3]
    const float* __restrict__ depth_values,  // [N, P]
    float* __restrict__ out,                 // [N*3 feat | N depth]
    int N)
{
    const int warp = threadIdx.x >> 5;
    const int lane = threadIdx.x & 31;
    const int ray  = blockIdx.x * WARPS_PER_BLOCK + warp;
    if (ray >= N) return;

    const float4* dens4 = (const float4*)(density      + (size_t)ray * P);
    const float4* dep4  = (const float4*)(depth_values + (size_t)ray * P);
    // lane's 4 samples' features: 12 consecutive floats at lane*12
    const float4* featL = (const float4*)(feature + (size_t)ray * P * C) + lane * 3;

    // ---- front-batched independent wide streaming loads (5 x LDG.128.CS) ----
    const float4 d4 = __ldcs(&dens4[lane]);
    const float4 z4 = __ldcs(&dep4[lane]);
    const float4 fA = __ldcs(&featL[0]);   // s0.r s0.g s0.b s1.r
    const float4 fB = __ldcs(&featL[1]);   // s1.g s1.b s2.r s2.g
    const float4 fC = __ldcs(&featL[2]);   // s2.b s3.r s3.g s3.b

    // ---- deltas ----
    const float znext = __shfl_down_sync(FULL_MASK, z4.x, 1);  // z[(lane+1)*4]
    const float dl0 = z4.y - z4.x;
    const float dl1 = z4.z - z4.y;
    const float dl2 = z4.w - z4.z;
    const float dl3 = (lane == 31) ? FAR_DELTA : (znext - z4.w);

    // ---- alpha / cumprod factors ----
    const float e0 = __expf(-fmaxf(d4.x, 0.0f) * dl0);
    const float e1 = __expf(-fmaxf(d4.y, 0.0f) * dl1);
    const float e2 = __expf(-fmaxf(d4.z, 0.0f) * dl2);
    const float e3 = __expf(-fmaxf(d4.w, 0.0f) * dl3);
    const float f0 = e0 + EPS, a0 = 1.0f - e0;
    const float f1 = e1 + EPS, a1 = 1.0f - e1;
    const float f2 = e2 + EPS, a2 = 1.0f - e2;
    const float f3 = e3 + EPS, a3 = 1.0f - e3;

    // per-lane exclusive prefix products
    const float pre1 = f0;
    const float pre2 = f0 * f1;
    const float pre3 = pre2 * f2;
    const float ltot = pre3 * f3;

    // ---- warp inclusive product scan over lane totals ----
    float v = ltot;
    #pragma unroll
    for (int off = 1; off < 32; off <<= 1) {
        const float t = __shfl_up_sync(FULL_MASK, v, off);
        if (lane >= off) v *= t;
    }
    float Lex = __shfl_up_sync(FULL_MASK, v, 1);  // product of preceding lanes
    if (lane == 0) Lex = 1.0f;

    // ---- weights ----
    const float w0 = Lex * a0;
    const float w1 = Lex * pre1 * a1;
    const float w2 = Lex * pre2 * a2;
    const float w3 = Lex * pre3 * a3;

    // ---- register-only accumulation (fixed permutation) ----
    float acc_r = w0 * fA.x + w1 * fA.w + w2 * fB.z + w3 * fC.y;
    float acc_g = w0 * fA.y + w1 * fB.x + w2 * fB.w + w3 * fC.z;
    float acc_b = w0 * fA.z + w1 * fB.y + w2 * fC.x + w3 * fC.w;
    float acc_d = w0 * z4.x + w1 * z4.y + w2 * z4.z + w3 * z4.w;

    // ---- warp reduction ----
    #pragma unroll
    for (int off = 16; off > 0; off >>= 1) {
        acc_r += __shfl_xor_sync(FULL_MASK, acc_r, off);
        acc_g += __shfl_xor_sync(FULL_MASK, acc_g, off);
        acc_b += __shfl_xor_sync(FULL_MASK, acc_b, off);
        acc_d += __shfl_xor_sync(FULL_MASK, acc_d, off);
    }

    if (lane == 0) {
        float* feat_out  = out;                   // [N, 3]
        float* depth_out = out + (size_t)N * C;   // [N]
        __stcs(&feat_out[(size_t)ray * C + 0], acc_r);
        __stcs(&feat_out[(size_t)ray * C + 1], acc_g);
        __stcs(&feat_out[(size_t)ray * C + 2], acc_b);
        __stcs(&depth_out[ray], acc_d);
    }
}

extern "C" void kernel_launch(void* const* d_in, const int* in_sizes, int n_in,
                              void* d_out, int out_size)
{
    const float* density      = (const float*)d_in[0];
    const float* feature      = (const float*)d_in[1];
    const float* depth_values = (const float*)d_in[2];
    float* out = (float*)d_out;

    const int N = in_sizes[0] / P;   // density is [N, P]

    const int blocks = (N + WARPS_PER_BLOCK - 1) / WARPS_PER_BLOCK;
    volume_render_kernel<<<blocks, 64>>>(density, feature, depth_values, out, N);
}